// round 10
// baseline (speedup 1.0000x reference)
#include <cuda_runtime.h>
#include <cstdint>

#define BB 1024
#define TT 512
#define HHH 64

typedef unsigned long long ull;

// Scratch (device globals — allocation-free per harness rules)
__device__ float g_bufA[(size_t)TT * BB * HHH];  // layer0 outputs [t][b][64]
__device__ float g_bufB[(size_t)TT * BB * HHH];  // layer1 outputs [t][b][64]
__device__ float g_hlast[BB * HHH];              // layer2 h at t=T-1

// ---- f32x2 packed helpers ----
__device__ __forceinline__ void upk2(ull v, float& lo, float& hi) {
    asm("mov.b64 {%0, %1}, %2;" : "=f"(lo), "=f"(hi) : "l"(v));
}
__device__ __forceinline__ ull fma2(ull a, ull b, ull c) {
    ull d; asm("fma.rn.f32x2 %0, %1, %2, %3;" : "=l"(d) : "l"(a), "l"(b), "l"(c)); return d;
}
__device__ __forceinline__ ull add2(ull a, ull b) {
    ull d; asm("add.rn.f32x2 %0, %1, %2;" : "=l"(d) : "l"(a), "l"(b)); return d;
}
__device__ __forceinline__ float hsum2(ull v) {
    float lo, hi; upk2(v, lo, hi); return lo + hi;
}
__device__ __forceinline__ float fsigmoid(float x) {
    return __fdividef(1.0f, 1.0f + __expf(-x));
}
__device__ __forceinline__ float ftanhf(float x) {
    float e = __expf(2.0f * x);
    return 1.0f - __fdividef(2.0f, e + 1.0f);
}

// swizzled position of unit/k index within a 72-float row (banks distinct)
__device__ __forceinline__ int P72(int k) { return k + 4 * (k >> 5); }

// ---------------------------------------------------------------------------
// Fused GRU layer: input projection + recurrence, ONE barrier per step.
// 128 blocks x 512 threads; block owns batch rows [8*blk, 8*blk+8).
// Thread (tau=(lane&3)|(warp<<2), s=lane>>2): owns gate triple {tau,64+tau,
// 128+tau} x k-slice [8s,8s+8) in the dot phase (W_hh, W_ih in REGISTERS,
// accumulating all 8 rows in 2 passes of 4), then a 3-round shfl_xor
// transpose-reduce (packed f32x2 adds) leaves the thread with the full gate
// sums of row ROWN = 4*s2+2*s0+s1 — it applies the GRU update with h kept in
// a register and publishes h via ping-pong swizzled hbuf. No psh, no second
// barrier. Output written coalesced from hbuf one step later.
// INW = 16 (layer0: x is [b][t][16]) or 64 (prev layer [t][b][64]).
// WALL = 1: write all timesteps; 0: only final h (to g_hlast).
// ---------------------------------------------------------------------------
template <int INW, int WALL>
__global__ void __launch_bounds__(512, 1) gru_fused(
    const float* __restrict__ xin,
    const float* __restrict__ Wih, const float* __restrict__ Whh,
    const float* __restrict__ bih, const float* __restrict__ bhh,
    float* __restrict__ outbuf)
{
    constexpr int XSTR = (INW == 64) ? 72 : 18;
    __shared__ float hbuf[2][8 * 72];
    __shared__ float xsh[2][8 * XSTR];

    const int tid  = threadIdx.x;
    const int warp = tid >> 5;
    const int lane = tid & 31;
    const int tau  = (lane & 3) | (warp << 2);   // 0..63
    const int s    = lane >> 2;                  // 0..7
    const int sb0  = s & 1, sb1 = (s >> 1) & 1, sb2 = s >> 2;
    const int ROWN = 4 * sb2 + 2 * sb0 + sb1;    // owned row (bijection)
    const int b0   = blockIdx.x * 8;
    const int hoff = 8 * s + 4 * (s >> 2);       // swizzled k offset

    // --- weights in registers ---
    ull wh[3][4];
#pragma unroll
    for (int g = 0; g < 3; g++)
#pragma unroll
        for (int kp = 0; kp < 4; kp++)
            wh[g][kp] = *(const ull*)(Whh + (size_t)(g * 64 + tau) * 64 + 8 * s + 2 * kp);

    constexpr int NXU = (INW == 64) ? 4 : 1;
    ull wx[3][NXU];
    if (INW == 64) {
#pragma unroll
        for (int g = 0; g < 3; g++)
#pragma unroll
            for (int kp = 0; kp < 4; kp++)
                wx[g][kp] = *(const ull*)(Wih + (size_t)(g * 64 + tau) * 64 + 8 * s + 2 * kp);
    } else {
#pragma unroll
        for (int g = 0; g < 3; g++)
            wx[g][0] = *(const ull*)(Wih + (size_t)(g * 64 + tau) * 16 + 2 * s);
    }

    // --- biases for owned unit (= tau) ---
    const float bR  = __ldg(bih + tau)      + __ldg(bhh + tau);
    const float bZ  = __ldg(bih + 64 + tau) + __ldg(bhh + 64 + tau);
    const float bNx = __ldg(bih + 128 + tau);
    const float bNh = __ldg(bhh + 128 + tau);

    // --- init: zero hbuf, stage x(0) ---
    for (int e = tid; e < 2 * 8 * 72; e += 512) ((float*)hbuf)[e] = 0.0f;
    {
        if (INW == 64) {
            int row = tid >> 6, c = tid & 63;
            xsh[0][row * 72 + P72(c)] =
                __ldg(xin + ((size_t)0 * BB + b0 + row) * 64 + c);
        } else if (tid < 128) {
            int row = tid >> 4, c = tid & 15;
            xsh[0][row * 18 + c] =
                __ldg(xin + ((size_t)(b0 + row) * TT + 0) * 16 + c);
        }
    }
    float h = 0.0f;
    __syncthreads();

    const int orow = tid >> 6;       // coalesced-store role
    const int ocol = tid & 63;
    const int ostride = P72(ocol);

#pragma unroll 1
    for (int t = 0; t < TT; ++t) {
        const int cur = t & 1;
        const float* hb = hbuf[cur];
        const float* xb = xsh[cur];

        // early: load next x into registers (latency hidden by dot phase)
        const int tn = (t + 1 < TT) ? t + 1 : t;
        float xnext = 0.0f;
        if (INW == 64) {
            xnext = __ldg(xin + ((size_t)tn * BB + b0 + orow) * 64 + ocol);
        } else if (tid < 128) {
            int row = tid >> 4, c = tid & 15;
            xnext = __ldg(xin + ((size_t)(b0 + row) * TT + tn) * 16 + c);
        }
        // early: out-store of h(t-1), coalesced from hbuf
        if (WALL && t > 0) {
            outbuf[((size_t)(t - 1) * BB + b0 + orow) * 64 + ocol] =
                hb[orow * 72 + ostride];
        }

        // ---- dot + reduce: 2 passes of 4 rows ----
        float fr, fz, fnh, fnx;
#pragma unroll
        for (int p = 0; p < 2; p++) {
            ull aR[4], aZ[4], aNh[4], aNx[4];
#pragma unroll
            for (int r = 0; r < 4; r++) { aR[r] = 0; aZ[r] = 0; aNh[r] = 0; aNx[r] = 0; }
#pragma unroll
            for (int r = 0; r < 4; r++) {
                const int row = p * 4 + r;
                const ulonglong2* hq = (const ulonglong2*)(hb + row * 72 + hoff);
                ulonglong2 A = hq[0], B = hq[1];
                aR[r]  = fma2(wh[0][0], A.x, aR[r]);  aR[r]  = fma2(wh[0][1], A.y, aR[r]);
                aR[r]  = fma2(wh[0][2], B.x, aR[r]);  aR[r]  = fma2(wh[0][3], B.y, aR[r]);
                aZ[r]  = fma2(wh[1][0], A.x, aZ[r]);  aZ[r]  = fma2(wh[1][1], A.y, aZ[r]);
                aZ[r]  = fma2(wh[1][2], B.x, aZ[r]);  aZ[r]  = fma2(wh[1][3], B.y, aZ[r]);
                aNh[r] = fma2(wh[2][0], A.x, aNh[r]); aNh[r] = fma2(wh[2][1], A.y, aNh[r]);
                aNh[r] = fma2(wh[2][2], B.x, aNh[r]); aNh[r] = fma2(wh[2][3], B.y, aNh[r]);
                if (INW == 64) {
                    const ulonglong2* xq = (const ulonglong2*)(xb + row * 72 + hoff);
                    ulonglong2 C = xq[0], D = xq[1];
                    aR[r]  = fma2(wx[0][0], C.x, aR[r]);  aR[r]  = fma2(wx[0][1], C.y, aR[r]);
                    aR[r]  = fma2(wx[0][2], D.x, aR[r]);  aR[r]  = fma2(wx[0][3], D.y, aR[r]);
                    aZ[r]  = fma2(wx[1][0], C.x, aZ[r]);  aZ[r]  = fma2(wx[1][1], C.y, aZ[r]);
                    aZ[r]  = fma2(wx[1][2], D.x, aZ[r]);  aZ[r]  = fma2(wx[1][3], D.y, aZ[r]);
                    aNx[r] = fma2(wx[2][0], C.x, aNx[r]); aNx[r] = fma2(wx[2][1], C.y, aNx[r]);
                    aNx[r] = fma2(wx[2][2], D.x, aNx[r]); aNx[r] = fma2(wx[2][3], D.y, aNx[r]);
                } else {
                    ull xv = *(const ull*)(xb + row * 18 + 2 * s);
                    aR[r]  = fma2(wx[0][0], xv, aR[r]);
                    aZ[r]  = fma2(wx[1][0], xv, aZ[r]);
                    aNx[r] = fma2(wx[2][0], xv, aNx[r]);
                }
            }
            // 3-round packed transpose-reduce; capture when p == sb2
#pragma unroll
            for (int pl = 0; pl < 4; pl++) {
                ull* a = (pl == 0) ? aR : (pl == 1) ? aZ : (pl == 2) ? aNh : aNx;
                ull s0v = sb0 ? a[0] : a[2];
                ull s1v = sb0 ? a[1] : a[3];
                ull r0v = __shfl_xor_sync(0xffffffffu, s0v, 4);
                ull r1v = __shfl_xor_sync(0xffffffffu, s1v, 4);
                ull b0v = add2(sb0 ? a[2] : a[0], r0v);   // row 2*sb0
                ull b1v = add2(sb0 ? a[3] : a[1], r1v);   // row 2*sb0+1
                ull s2v = sb1 ? b0v : b1v;
                ull r2v = __shfl_xor_sync(0xffffffffu, s2v, 8);
                ull cv  = add2(sb1 ? b1v : b0v, r2v);     // row 2*sb0+sb1
                ull dv  = add2(cv, __shfl_xor_sync(0xffffffffu, cv, 16));
                if (p == sb2) {
                    float v = hsum2(dv);
                    if (pl == 0) fr = v; else if (pl == 1) fz = v;
                    else if (pl == 2) fnh = v; else fnx = v;
                }
            }
        }

        // ---- update (in-register h), publish to hbuf[nxt] ----
        float r = fsigmoid(fr + bR);
        float z = fsigmoid(fz + bZ);
        float n = ftanhf(fnx + bNx + r * (fnh + bNh));
        h = fmaf(z, h - n, n);

        float* hn = hbuf[cur ^ 1];
        hn[ROWN * 72 + P72(tau)] = h;

        // stage next x
        float* xn = xsh[cur ^ 1];
        if (INW == 64) {
            xn[orow * 72 + P72(ocol)] = xnext;
        } else if (tid < 128) {
            int row = tid >> 4, c = tid & 15;
            xn[row * 18 + c] = xnext;
        }
        __syncthreads();
    }

    // final h(T-1) lives in hbuf[TT & 1] = hbuf[0]
    if (WALL) {
        outbuf[((size_t)(TT - 1) * BB + b0 + orow) * 64 + ocol] =
            hbuf[0][orow * 72 + ostride];
    } else {
        outbuf[(size_t)(b0 + orow) * 64 + ocol] = hbuf[0][orow * 72 + ostride];
    }
}

// ---------------------------------------------------------------------------
// Head: y[b] = fc2_b + fc2_w . relu(fc1_w @ h_last[b] + fc1_b)
// ---------------------------------------------------------------------------
__global__ void __launch_bounds__(256) head_kernel(
    const float* __restrict__ fc1w, const float* __restrict__ fc1b,
    const float* __restrict__ fc2w, const float* __restrict__ fc2b,
    float* __restrict__ y)
{
    __shared__ float s1[32 * 64];
    __shared__ float sb1[32];
    __shared__ float sw2[32];
    const int tid = threadIdx.x;
    for (int e = tid; e < 2048; e += 256) s1[e] = fc1w[e];
    if (tid < 32) { sb1[tid] = fc1b[tid]; sw2[tid] = fc2w[tid]; }
    __syncthreads();

    const int b = blockIdx.x * 256 + tid;
    const float* hp = g_hlast + (size_t)b * HHH;
    float hv[64];
#pragma unroll
    for (int q = 0; q < 16; q++) {
        float4 v = *(const float4*)(hp + q * 4);
        hv[q * 4] = v.x; hv[q * 4 + 1] = v.y; hv[q * 4 + 2] = v.z; hv[q * 4 + 3] = v.w;
    }
    float acc = __ldg(fc2b);
#pragma unroll
    for (int j = 0; j < 32; j++) {
        float sacc = sb1[j];
#pragma unroll
        for (int k = 0; k < 64; k++) sacc = fmaf(s1[j * 64 + k], hv[k], sacc);
        acc = fmaf(sw2[j], fmaxf(sacc, 0.0f), acc);
    }
    y[b] = acc;
}

// ---------------------------------------------------------------------------
extern "C" void kernel_launch(void* const* d_in, const int* in_sizes, int n_in,
                              void* d_out, int out_size)
{
    const float* x    = (const float*)d_in[0];
    const float* Wih0 = (const float*)d_in[1];
    const float* Whh0 = (const float*)d_in[2];
    const float* bih0 = (const float*)d_in[3];
    const float* bhh0 = (const float*)d_in[4];
    const float* Wih1 = (const float*)d_in[5];
    const float* Whh1 = (const float*)d_in[6];
    const float* bih1 = (const float*)d_in[7];
    const float* bhh1 = (const float*)d_in[8];
    const float* Wih2 = (const float*)d_in[9];
    const float* Whh2 = (const float*)d_in[10];
    const float* bih2 = (const float*)d_in[11];
    const float* bhh2 = (const float*)d_in[12];
    const float* fc1w = (const float*)d_in[13];
    const float* fc1b = (const float*)d_in[14];
    const float* fc2w = (const float*)d_in[15];
    const float* fc2b = (const float*)d_in[16];
    float* y = (float*)d_out;
    (void)in_sizes; (void)n_in; (void)out_size;

    float *bufA = nullptr, *bufB = nullptr, *hlast = nullptr;
    cudaGetSymbolAddress((void**)&bufA, g_bufA);
    cudaGetSymbolAddress((void**)&bufB, g_bufB);
    cudaGetSymbolAddress((void**)&hlast, g_hlast);

    gru_fused<16, 1><<<128, 512>>>(x,    Wih0, Whh0, bih0, bhh0, bufA);
    gru_fused<64, 1><<<128, 512>>>(bufA, Wih1, Whh1, bih1, bhh1, bufB);
    gru_fused<64, 0><<<128, 512>>>(bufB, Wih2, Whh2, bih2, bhh2, hlast);
    head_kernel<<<4, 256>>>(fc1w, fc1b, fc2w, fc2b, y);
}